// round 3
// baseline (speedup 1.0000x reference)
#include <cuda_runtime.h>
#include <cstdint>

#define NMAX 50048
#define EMAX 800256
#define H 128

__device__ int   g_is64;
__device__ int   g_deg[NMAX];
__device__ int   g_offs[NMAX + 1];
__device__ int   g_cur[NMAX];
__device__ int   g_adj[EMAX];
__device__ float g_dinv[NMAX];
__device__ __align__(16) float g_hh[(size_t)NMAX * H];
__device__ __align__(16) float g_y[(size_t)NMAX * H];
__device__ float g_stats[512];
__device__ float g_bnS[H];
__device__ float g_bnH[H];

// ---------------------------------------------------------------------------
// dtype probe: int64 edge_index has zero high-words at odd int32 positions.
__global__ void probe_kernel(const int* __restrict__ ei32, int e) {
    __shared__ int nz;
    if (threadIdx.x == 0) nz = 0;
    __syncthreads();
    int i = threadIdx.x;                  // 1024 threads probe odd positions
    int pos = 2 * i + 1;
    if (pos < 2 * e && ei32[pos] != 0) atomicAdd(&nz, 1);
    __syncthreads();
    if (threadIdx.x == 0) g_is64 = (nz == 0) ? 1 : 0;
}

__device__ __forceinline__ int load_idx(const void* eiv, size_t pos, int n) {
    int v;
    if (g_is64) v = (int)((const long long*)eiv)[pos];
    else        v = ((const int*)eiv)[pos];
    return min(max(v, 0), n - 1);
}

// ---------------------------------------------------------------------------
__global__ void zero_kernel(int n) {
    int i = blockIdx.x * blockDim.x + threadIdx.x;
    if (i < n) g_deg[i] = 0;
    if (i < 512) g_stats[i] = 0.0f;
}

__global__ void count_kernel(const void* __restrict__ eiv, int e, int n) {
    int i = blockIdx.x * blockDim.x + threadIdx.x;
    if (i < e) {
        int d = load_idx(eiv, (size_t)e + i, n);
        atomicAdd(&g_deg[d], 1);
    }
}

// single-block exclusive scan of g_deg -> g_offs, g_cur
__global__ void scan_kernel(int n) {
    __shared__ int part[1024];
    int tid = threadIdx.x;
    int chunk = (n + 1023) >> 10;
    int s0 = min(tid * chunk, n);
    int s1 = min(s0 + chunk, n);
    int s = 0;
    for (int i = s0; i < s1; i++) s += g_deg[i];
    part[tid] = s;
    __syncthreads();
    for (int off = 1; off < 1024; off <<= 1) {
        int v = (tid >= off) ? part[tid - off] : 0;
        __syncthreads();
        part[tid] += v;
        __syncthreads();
    }
    int base = (tid > 0) ? part[tid - 1] : 0;
    int run = base;
    for (int i = s0; i < s1; i++) {
        g_offs[i] = run;
        g_cur[i] = run;
        run += g_deg[i];
    }
    if (tid == 1023) g_offs[n] = part[1023];
}

__global__ void dinv_kernel(int n) {
    int i = blockIdx.x * blockDim.x + threadIdx.x;
    if (i < n) g_dinv[i] = rsqrtf((float)g_deg[i] + 1.0f);  // +1 self-loop
}

__global__ void fill_kernel(const void* __restrict__ eiv, int e, int n) {
    int i = blockIdx.x * blockDim.x + threadIdx.x;
    if (i < e) {
        int s = load_idx(eiv, (size_t)i, n);
        int d = load_idx(eiv, (size_t)e + i, n);
        int p = atomicAdd(&g_cur[d], 1);
        if (p >= 0 && p < EMAX) g_adj[p] = s;
    }
}

// ---------------------------------------------------------------------------
// GEMM: g_hh[row] = dinv[row] * ( f(X[row]) @ W )
//   mode 0: X = Xext (layer 1), f = identity
//   mode 1: X = g_y  (layer 2), f = relu(bn affine) using g_bnS/g_bnH
// 128x128 output tile, 256 threads, 4x16 per thread, K chunks of 32.
#define KC 32
__global__ void __launch_bounds__(256)
gemm_kernel(const float* __restrict__ Xext, const float* __restrict__ W,
            int n, int mode) {
    __shared__ float Xs[128][KC + 1];
    __shared__ float Ws[KC][128];
    __shared__ float bnS[H], bnH[H];

    const float* X = (mode == 1) ? (const float*)g_y : Xext;

    int tid = threadIdx.x;
    int row0 = blockIdx.x * 128;
    int tx = tid & 7;    // col group: 16 cols
    int ty = tid >> 3;   // row group: 4 rows

    if (tid < 128) { bnS[tid] = g_bnS[tid]; bnH[tid] = g_bnH[tid]; }

    float acc[4][16];
    #pragma unroll
    for (int r = 0; r < 4; r++)
        #pragma unroll
        for (int c = 0; c < 16; c++) acc[r][c] = 0.0f;

    for (int kc = 0; kc < H; kc += KC) {
        __syncthreads();
        // stage X chunk: 128 rows x 32 cols = 1024 float4, 4 per thread
        #pragma unroll
        for (int i = tid; i < 128 * (KC / 4); i += 256) {
            int r = i >> 3;
            int c4 = i & 7;
            float4 v = make_float4(0.f, 0.f, 0.f, 0.f);
            int grow = row0 + r;
            if (grow < n)
                v = *(const float4*)(X + (size_t)grow * H + kc + c4 * 4);
            if (mode == 1) {
                int c = kc + c4 * 4;
                v.x = fmaxf(fmaf(v.x, bnS[c + 0], bnH[c + 0]), 0.f);
                v.y = fmaxf(fmaf(v.y, bnS[c + 1], bnH[c + 1]), 0.f);
                v.z = fmaxf(fmaf(v.z, bnS[c + 2], bnH[c + 2]), 0.f);
                v.w = fmaxf(fmaf(v.w, bnS[c + 3], bnH[c + 3]), 0.f);
            }
            Xs[r][c4 * 4 + 0] = v.x;
            Xs[r][c4 * 4 + 1] = v.y;
            Xs[r][c4 * 4 + 2] = v.z;
            Xs[r][c4 * 4 + 3] = v.w;
        }
        // stage W chunk: 32 rows x 128 cols
        #pragma unroll
        for (int i = tid; i < KC * 32; i += 256) {
            int r = i >> 5;
            int c4 = i & 31;
            *(float4*)&Ws[r][c4 * 4] =
                *(const float4*)(W + (size_t)(kc + r) * H + c4 * 4);
        }
        __syncthreads();

        #pragma unroll
        for (int k = 0; k < KC; k++) {
            float a[4];
            #pragma unroll
            for (int r = 0; r < 4; r++) a[r] = Xs[ty * 4 + r][k];
            float b[16];
            #pragma unroll
            for (int j = 0; j < 4; j++) {
                float4 bv = *(const float4*)&Ws[k][tx * 16 + j * 4];
                b[j * 4 + 0] = bv.x; b[j * 4 + 1] = bv.y;
                b[j * 4 + 2] = bv.z; b[j * 4 + 3] = bv.w;
            }
            #pragma unroll
            for (int r = 0; r < 4; r++)
                #pragma unroll
                for (int c = 0; c < 16; c++)
                    acc[r][c] = fmaf(a[r], b[c], acc[r][c]);
        }
    }

    #pragma unroll
    for (int r = 0; r < 4; r++) {
        int row = row0 + ty * 4 + r;
        if (row < n) {
            float dv = g_dinv[row];
            float* o = g_hh + (size_t)row * H + tx * 16;
            #pragma unroll
            for (int c = 0; c < 16; c += 4) {
                float4 v;
                v.x = acc[r][c + 0] * dv;
                v.y = acc[r][c + 1] * dv;
                v.z = acc[r][c + 2] * dv;
                v.w = acc[r][c + 3] * dv;
                *(float4*)(o + c) = v;
            }
        }
    }
}

// ---------------------------------------------------------------------------
// aggregation: one warp per node, float4 per lane
// y[d] = dinv[d] * ( hh[d] + sum_{s in N(d)} hh[s] ) + bias
__global__ void agg_kernel(const float* __restrict__ bias, int n) {
    int warp = (blockIdx.x * blockDim.x + threadIdx.x) >> 5;
    int lane = threadIdx.x & 31;
    if (warp >= n) return;
    int d = warp;

    const float4* hh4 = (const float4*)g_hh;
    float4 acc = hh4[(size_t)d * 32 + lane];   // self-loop term
    int beg = g_offs[d];
    int end = g_offs[d + 1];

    for (int j0 = beg; j0 < end; j0 += 32) {
        int idx = (j0 + lane < end) ? g_adj[j0 + lane] : 0;
        int cnt = min(32, end - j0);
        int t = 0;
        for (; t + 3 < cnt; t += 4) {
            int s0 = __shfl_sync(0xffffffffu, idx, t + 0);
            int s1 = __shfl_sync(0xffffffffu, idx, t + 1);
            int s2 = __shfl_sync(0xffffffffu, idx, t + 2);
            int s3 = __shfl_sync(0xffffffffu, idx, t + 3);
            float4 v0 = hh4[(size_t)s0 * 32 + lane];
            float4 v1 = hh4[(size_t)s1 * 32 + lane];
            float4 v2 = hh4[(size_t)s2 * 32 + lane];
            float4 v3 = hh4[(size_t)s3 * 32 + lane];
            acc.x += v0.x + v1.x + v2.x + v3.x;
            acc.y += v0.y + v1.y + v2.y + v3.y;
            acc.z += v0.z + v1.z + v2.z + v3.z;
            acc.w += v0.w + v1.w + v2.w + v3.w;
        }
        for (; t < cnt; t++) {
            int s = __shfl_sync(0xffffffffu, idx, t);
            float4 v = hh4[(size_t)s * 32 + lane];
            acc.x += v.x; acc.y += v.y; acc.z += v.z; acc.w += v.w;
        }
    }

    float dv = g_dinv[d];
    float4 bb = *(const float4*)(bias + lane * 4);
    float4 out;
    out.x = fmaf(acc.x, dv, bb.x);
    out.y = fmaf(acc.y, dv, bb.y);
    out.z = fmaf(acc.z, dv, bb.z);
    out.w = fmaf(acc.w, dv, bb.w);
    ((float4*)g_y)[(size_t)d * 32 + lane] = out;
}

// ---------------------------------------------------------------------------
__global__ void stats_kernel(int n, int slot) {
    int c = threadIdx.x;  // 128 threads = 128 columns
    int r0 = blockIdx.x * 256;
    int r1 = min(r0 + 256, n);
    float s = 0.f, s2 = 0.f;
    for (int r = r0; r < r1; r++) {
        float v = g_y[(size_t)r * H + c];
        s += v;
        s2 += v * v;
    }
    atomicAdd(&g_stats[slot + c], s);
    atomicAdd(&g_stats[slot + 128 + c], s2);
}

__global__ void bnparam_kernel(const float* __restrict__ g,
                               const float* __restrict__ beta,
                               int n, int slot) {
    int c = threadIdx.x;
    float inv_n = 1.0f / (float)n;
    float mu = g_stats[slot + c] * inv_n;
    float var = g_stats[slot + 128 + c] * inv_n - mu * mu;
    float istd = rsqrtf(var + 1e-5f);
    float sc = g[c] * istd;
    g_bnS[c] = sc;
    g_bnH[c] = beta[c] - mu * sc;
}

__global__ void out_kernel(float* __restrict__ out, int n) {
    int i = blockIdx.x * blockDim.x + threadIdx.x;
    if (i >= n * 32) return;
    int c = (i & 31) * 4;
    float4 v = ((const float4*)g_y)[i];
    v.x = fmaxf(fmaf(v.x, g_bnS[c + 0], g_bnH[c + 0]), 0.f);
    v.y = fmaxf(fmaf(v.y, g_bnS[c + 1], g_bnH[c + 1]), 0.f);
    v.z = fmaxf(fmaf(v.z, g_bnS[c + 2], g_bnH[c + 2]), 0.f);
    v.w = fmaxf(fmaf(v.w, g_bnS[c + 3], g_bnH[c + 3]), 0.f);
    ((float4*)out)[i] = v;
}

// ---------------------------------------------------------------------------
extern "C" void kernel_launch(void* const* d_in, const int* in_sizes, int n_in,
                              void* d_out, int out_size) {
    const float* node_feat = (const float*)d_in[0];
    const void*  ei        = d_in[1];
    const float* W1   = (const float*)d_in[2];
    const float* b1   = (const float*)d_in[3];
    const float* W2   = (const float*)d_in[4];
    const float* b2   = (const float*)d_in[5];
    const float* g1   = (const float*)d_in[6];
    const float* beta1= (const float*)d_in[7];
    const float* g2   = (const float*)d_in[8];
    const float* beta2= (const float*)d_in[9];

    int n = in_sizes[0] / H;
    int e = in_sizes[1] / 2;

    int nb256 = (n + 255) / 256;
    int eb256 = (e + 255) / 256;
    int gemm_blocks = (n + 127) / 128;
    int agg_blocks = (n * 32 + 255) / 256;

    // graph prep (shared by both layers)
    probe_kernel<<<1, 1024>>>((const int*)ei, e);
    zero_kernel<<<nb256, 256>>>(n);
    count_kernel<<<eb256, 256>>>(ei, e, n);
    scan_kernel<<<1, 1024>>>(n);
    dinv_kernel<<<nb256, 256>>>(n);
    fill_kernel<<<eb256, 256>>>(ei, e, n);

    // layer 1
    gemm_kernel<<<gemm_blocks, 256>>>(node_feat, W1, n, 0);
    agg_kernel<<<agg_blocks, 256>>>(b1, n);
    stats_kernel<<<nb256, 128>>>(n, 0);
    bnparam_kernel<<<1, 128>>>(g1, beta1, n, 0);

    // layer 2 (BN+relu of layer-1 fused into the X-tile load)
    gemm_kernel<<<gemm_blocks, 256>>>(nullptr, W2, n, 1);
    agg_kernel<<<agg_blocks, 256>>>(b2, n);
    stats_kernel<<<nb256, 128>>>(n, 256);
    bnparam_kernel<<<1, 128>>>(g2, beta2, n, 256);

    out_kernel<<<agg_blocks, 256>>>((float*)d_out, n);
}

// round 4
// speedup vs baseline: 1.9498x; 1.9498x over previous
#include <cuda_runtime.h>
#include <cstdint>

#define NMAX 50048
#define EMAX 800256
#define H 128
#define SB 256                      // scan block size
#define NBMAX ((NMAX + SB - 1) / SB)

__device__ int   g_is64;
__device__ int   g_deg[NMAX];
__device__ int   g_offs[NMAX + 1];
__device__ int   g_cur[NMAX];
__device__ int   g_adj[EMAX];
__device__ int   g_bsum[NBMAX];
__device__ int   g_bbase[NBMAX];
__device__ float g_dinv[NMAX];
__device__ __align__(16) float g_hh[(size_t)NMAX * H];
__device__ __align__(16) float g_y[(size_t)NMAX * H];
__device__ float g_stats[512];
__device__ float g_bnS[H];
__device__ float g_bnH[H];

// ---------------------------------------------------------------------------
// dtype probe: int64 edge_index has zero high-words at odd int32 positions.
__global__ void probe_kernel(const int* __restrict__ ei32, int e) {
    __shared__ int nz;
    if (threadIdx.x == 0) nz = 0;
    __syncthreads();
    int pos = 2 * threadIdx.x + 1;
    if (pos < 2 * e && ei32[pos] != 0) atomicAdd(&nz, 1);
    __syncthreads();
    if (threadIdx.x == 0) g_is64 = (nz == 0) ? 1 : 0;
}

__device__ __forceinline__ int load_idx(const void* eiv, size_t pos, int n) {
    int v;
    if (g_is64) v = (int)((const long long*)eiv)[pos];
    else        v = ((const int*)eiv)[pos];
    return min(max(v, 0), n - 1);
}

// ---------------------------------------------------------------------------
__global__ void zero_kernel(int n) {
    int i = blockIdx.x * blockDim.x + threadIdx.x;
    if (i < n) g_deg[i] = 0;
    if (i < 512) g_stats[i] = 0.0f;
}

__global__ void count_kernel(const void* __restrict__ eiv, int e, int n) {
    int i = blockIdx.x * blockDim.x + threadIdx.x;
    if (i < e) {
        int d = load_idx(eiv, (size_t)e + i, n);
        atomicAdd(&g_deg[d], 1);
    }
}

// phase 1: per-block sums of g_deg
__global__ void scan1_kernel(int n) {
    __shared__ int ws[8];
    int i = blockIdx.x * SB + threadIdx.x;
    int v = (i < n) ? g_deg[i] : 0;
    #pragma unroll
    for (int o = 16; o > 0; o >>= 1) v += __shfl_down_sync(0xffffffffu, v, o);
    if ((threadIdx.x & 31) == 0) ws[threadIdx.x >> 5] = v;
    __syncthreads();
    if (threadIdx.x < 8) {
        int s = ws[threadIdx.x];
        #pragma unroll
        for (int o = 4; o > 0; o >>= 1) s += __shfl_down_sync(0xffu, s, o);
        if (threadIdx.x == 0) g_bsum[blockIdx.x] = s;
    }
}

// phase 2: exclusive scan of block sums (single small block)
__global__ void scan2_kernel(int nb) {
    __shared__ int sh[NBMAX];
    int t = threadIdx.x;
    if (t < nb) sh[t] = g_bsum[t];
    __syncthreads();
    for (int o = 1; o < nb; o <<= 1) {
        int v = (t >= o && t < nb) ? sh[t - o] : 0;
        __syncthreads();
        if (t < nb) sh[t] += v;
        __syncthreads();
    }
    if (t < nb) g_bbase[t] = (t > 0) ? sh[t - 1] : 0;
}

// phase 3: per-block local exclusive scan + base -> offs/cur; also dinv
__global__ void scan3_kernel(int n) {
    __shared__ int sh[SB];
    int t = threadIdx.x;
    int i = blockIdx.x * SB + t;
    int d = (i < n) ? g_deg[i] : 0;
    sh[t] = d;
    __syncthreads();
    #pragma unroll
    for (int o = 1; o < SB; o <<= 1) {
        int v = (t >= o) ? sh[t - o] : 0;
        __syncthreads();
        sh[t] += v;
        __syncthreads();
    }
    int incl = sh[t];
    int base = g_bbase[blockIdx.x];
    if (i < n) {
        int off = base + incl - d;   // exclusive
        g_offs[i] = off;
        g_cur[i] = off;
        g_dinv[i] = rsqrtf((float)d + 1.0f);
        if (i == n - 1) g_offs[n] = base + incl;
    }
}

__global__ void fill_kernel(const void* __restrict__ eiv, int e, int n) {
    int i = blockIdx.x * blockDim.x + threadIdx.x;
    if (i < e) {
        int s = load_idx(eiv, (size_t)i, n);
        int d = load_idx(eiv, (size_t)e + i, n);
        int p = atomicAdd(&g_cur[d], 1);
        if (p >= 0 && p < EMAX) g_adj[p] = s;
    }
}

// ---------------------------------------------------------------------------
// GEMM: g_hh[row] = dinv[row] * ( f(X[row]) @ W )
//   mode 0: X = Xext (layer 1), f = identity
//   mode 1: X = g_y  (layer 2), f = relu(bn affine)
// 128x128 tile, 256 threads, 4 rows x 16 cols per thread (cols tx*2 + j*16),
// packed fma.rn.f32x2 accumulators (exact fp32, 2x FFMA throughput).
#define KC 32
__global__ void __launch_bounds__(256)
gemm_kernel(const float* __restrict__ Xext, const float* __restrict__ W,
            int n, int mode) {
    __shared__ float Xs[128][KC + 1];
    __shared__ float Ws[KC][128];
    __shared__ float bnS[H], bnH[H];

    const float* X = (mode == 1) ? (const float*)g_y : Xext;

    int tid = threadIdx.x;
    int row0 = blockIdx.x * 128;
    int tx = tid & 7;    // col pairs: cols tx*2 + j*16, j=0..7
    int ty = tid >> 3;   // rows ty*4 .. ty*4+3

    if (tid < 128) { bnS[tid] = g_bnS[tid]; bnH[tid] = g_bnH[tid]; }

    unsigned long long acc[4][8];
    #pragma unroll
    for (int r = 0; r < 4; r++)
        #pragma unroll
        for (int j = 0; j < 8; j++) acc[r][j] = 0ull;

    for (int kc = 0; kc < H; kc += KC) {
        __syncthreads();
        // stage X chunk: 128 rows x 32 cols
        #pragma unroll
        for (int i = tid; i < 128 * (KC / 4); i += 256) {
            int r = i >> 3;
            int c4 = i & 7;
            float4 v = make_float4(0.f, 0.f, 0.f, 0.f);
            int grow = row0 + r;
            if (grow < n)
                v = *(const float4*)(X + (size_t)grow * H + kc + c4 * 4);
            if (mode == 1) {
                int c = kc + c4 * 4;
                v.x = fmaxf(fmaf(v.x, bnS[c + 0], bnH[c + 0]), 0.f);
                v.y = fmaxf(fmaf(v.y, bnS[c + 1], bnH[c + 1]), 0.f);
                v.z = fmaxf(fmaf(v.z, bnS[c + 2], bnH[c + 2]), 0.f);
                v.w = fmaxf(fmaf(v.w, bnS[c + 3], bnH[c + 3]), 0.f);
            }
            Xs[r][c4 * 4 + 0] = v.x;
            Xs[r][c4 * 4 + 1] = v.y;
            Xs[r][c4 * 4 + 2] = v.z;
            Xs[r][c4 * 4 + 3] = v.w;
        }
        // stage W chunk: 32 rows x 128 cols
        #pragma unroll
        for (int i = tid; i < KC * 32; i += 256) {
            int r = i >> 5;
            int c4 = i & 31;
            *(float4*)&Ws[r][c4 * 4] =
                *(const float4*)(W + (size_t)(kc + r) * H + c4 * 4);
        }
        __syncthreads();

        #pragma unroll
        for (int k = 0; k < KC; k++) {
            unsigned long long a[4];
            #pragma unroll
            for (int r = 0; r < 4; r++) {
                unsigned int ai = __float_as_uint(Xs[ty * 4 + r][k]);
                asm("mov.b64 %0, {%1, %1};" : "=l"(a[r]) : "r"(ai));
            }
            // b[j] = Ws[k][j*16 + tx*2 .. +1]  (conflict-free: consecutive
            // 8B words across tx within each j)
            const unsigned long long* bp = (const unsigned long long*)&Ws[k][0];
            unsigned long long b[8];
            #pragma unroll
            for (int j = 0; j < 8; j++) b[j] = bp[j * 8 + tx];
            #pragma unroll
            for (int r = 0; r < 4; r++)
                #pragma unroll
                for (int j = 0; j < 8; j++)
                    asm("fma.rn.f32x2 %0, %1, %2, %0;"
                        : "+l"(acc[r][j]) : "l"(a[r]), "l"(b[j]));
        }
    }

    #pragma unroll
    for (int r = 0; r < 4; r++) {
        int row = row0 + ty * 4 + r;
        if (row < n) {
            float dv = g_dinv[row];
            float* o = g_hh + (size_t)row * H + tx * 2;
            #pragma unroll
            for (int j = 0; j < 8; j++) {
                unsigned int lo, hi;
                asm("mov.b64 {%0, %1}, %2;" : "=r"(lo), "=r"(hi) : "l"(acc[r][j]));
                float2 v;
                v.x = __uint_as_float(lo) * dv;
                v.y = __uint_as_float(hi) * dv;
                *(float2*)(o + j * 16) = v;
            }
        }
    }
}

// ---------------------------------------------------------------------------
// aggregation: one warp per node, float4 per lane
__global__ void agg_kernel(const float* __restrict__ bias, int n) {
    int warp = (blockIdx.x * blockDim.x + threadIdx.x) >> 5;
    int lane = threadIdx.x & 31;
    if (warp >= n) return;
    int d = warp;

    const float4* hh4 = (const float4*)g_hh;
    float4 acc = hh4[(size_t)d * 32 + lane];   // self-loop term
    int beg = g_offs[d];
    int end = g_offs[d + 1];

    for (int j0 = beg; j0 < end; j0 += 32) {
        int idx = (j0 + lane < end) ? g_adj[j0 + lane] : 0;
        int cnt = min(32, end - j0);
        int t = 0;
        for (; t + 3 < cnt; t += 4) {
            int s0 = __shfl_sync(0xffffffffu, idx, t + 0);
            int s1 = __shfl_sync(0xffffffffu, idx, t + 1);
            int s2 = __shfl_sync(0xffffffffu, idx, t + 2);
            int s3 = __shfl_sync(0xffffffffu, idx, t + 3);
            float4 v0 = hh4[(size_t)s0 * 32 + lane];
            float4 v1 = hh4[(size_t)s1 * 32 + lane];
            float4 v2 = hh4[(size_t)s2 * 32 + lane];
            float4 v3 = hh4[(size_t)s3 * 32 + lane];
            acc.x += v0.x + v1.x + v2.x + v3.x;
            acc.y += v0.y + v1.y + v2.y + v3.y;
            acc.z += v0.z + v1.z + v2.z + v3.z;
            acc.w += v0.w + v1.w + v2.w + v3.w;
        }
        for (; t < cnt; t++) {
            int s = __shfl_sync(0xffffffffu, idx, t);
            float4 v = hh4[(size_t)s * 32 + lane];
            acc.x += v.x; acc.y += v.y; acc.z += v.z; acc.w += v.w;
        }
    }

    float dv = g_dinv[d];
    float4 bb = *(const float4*)(bias + lane * 4);
    float4 out;
    out.x = fmaf(acc.x, dv, bb.x);
    out.y = fmaf(acc.y, dv, bb.y);
    out.z = fmaf(acc.z, dv, bb.z);
    out.w = fmaf(acc.w, dv, bb.w);
    ((float4*)g_y)[(size_t)d * 32 + lane] = out;
}

// ---------------------------------------------------------------------------
__global__ void stats_kernel(int n, int slot) {
    int c = threadIdx.x;
    int r0 = blockIdx.x * 256;
    int r1 = min(r0 + 256, n);
    float s = 0.f, s2 = 0.f;
    for (int r = r0; r < r1; r++) {
        float v = g_y[(size_t)r * H + c];
        s += v;
        s2 += v * v;
    }
    atomicAdd(&g_stats[slot + c], s);
    atomicAdd(&g_stats[slot + 128 + c], s2);
}

__global__ void bnparam_kernel(const float* __restrict__ g,
                               const float* __restrict__ beta,
                               int n, int slot) {
    int c = threadIdx.x;
    float inv_n = 1.0f / (float)n;
    float mu = g_stats[slot + c] * inv_n;
    float var = g_stats[slot + 128 + c] * inv_n - mu * mu;
    float istd = rsqrtf(var + 1e-5f);
    float sc = g[c] * istd;
    g_bnS[c] = sc;
    g_bnH[c] = beta[c] - mu * sc;
}

__global__ void out_kernel(float* __restrict__ out, int n) {
    int i = blockIdx.x * blockDim.x + threadIdx.x;
    if (i >= n * 32) return;
    int c = (i & 31) * 4;
    float4 v = ((const float4*)g_y)[i];
    v.x = fmaxf(fmaf(v.x, g_bnS[c + 0], g_bnH[c + 0]), 0.f);
    v.y = fmaxf(fmaf(v.y, g_bnS[c + 1], g_bnH[c + 1]), 0.f);
    v.z = fmaxf(fmaf(v.z, g_bnS[c + 2], g_bnH[c + 2]), 0.f);
    v.w = fmaxf(fmaf(v.w, g_bnS[c + 3], g_bnH[c + 3]), 0.f);
    ((float4*)out)[i] = v;
}

// ---------------------------------------------------------------------------
extern "C" void kernel_launch(void* const* d_in, const int* in_sizes, int n_in,
                              void* d_out, int out_size) {
    const float* node_feat = (const float*)d_in[0];
    const void*  ei        = d_in[1];
    const float* W1   = (const float*)d_in[2];
    const float* b1   = (const float*)d_in[3];
    const float* W2   = (const float*)d_in[4];
    const float* b2   = (const float*)d_in[5];
    const float* g1   = (const float*)d_in[6];
    const float* beta1= (const float*)d_in[7];
    const float* g2   = (const float*)d_in[8];
    const float* beta2= (const float*)d_in[9];

    int n = in_sizes[0] / H;
    int e = in_sizes[1] / 2;

    int nb256 = (n + 255) / 256;
    int eb256 = (e + 255) / 256;
    int gemm_blocks = (n + 127) / 128;
    int agg_blocks = (n * 32 + 255) / 256;
    int scan_blocks = (n + SB - 1) / SB;

    // graph prep
    probe_kernel<<<1, 1024>>>((const int*)ei, e);
    zero_kernel<<<nb256, 256>>>(n);
    count_kernel<<<eb256, 256>>>(ei, e, n);
    scan1_kernel<<<scan_blocks, SB>>>(n);
    scan2_kernel<<<1, NBMAX>>>(scan_blocks);
    scan3_kernel<<<scan_blocks, SB>>>(n);
    fill_kernel<<<eb256, 256>>>(ei, e, n);

    // layer 1
    gemm_kernel<<<gemm_blocks, 256>>>(node_feat, W1, n, 0);
    agg_kernel<<<agg_blocks, 256>>>(b1, n);
    stats_kernel<<<nb256, 128>>>(n, 0);
    bnparam_kernel<<<1, 128>>>(g1, beta1, n, 0);

    // layer 2 (BN+relu fused into GEMM X-tile load)
    gemm_kernel<<<gemm_blocks, 256>>>(nullptr, W2, n, 1);
    agg_kernel<<<agg_blocks, 256>>>(b2, n);
    stats_kernel<<<nb256, 128>>>(n, 256);
    bnparam_kernel<<<1, 128>>>(g2, beta2, n, 256);

    out_kernel<<<agg_blocks, 256>>>((float*)d_out, n);
}

// round 5
// speedup vs baseline: 1.9651x; 1.0079x over previous
#include <cuda_runtime.h>
#include <cstdint>

#define NMAX 50048
#define EMAX 800256
#define H 128
#define SB 256
#define NBMAX ((NMAX + SB - 1) / SB)
#define NBUCKET 64

__device__ int   g_is64;
__device__ int   g_deg[NMAX];
__device__ int   g_offs[NMAX + 1];
__device__ int   g_cur[NMAX];
__device__ int   g_adj[EMAX];
__device__ int   g_bsum[NBMAX];
__device__ int   g_bbase[NBMAX];
__device__ float g_dinv[NMAX];
__device__ __align__(16) float g_hh[(size_t)NMAX * H];
__device__ __align__(16) float g_y[(size_t)NMAX * H];
__device__ float g_stats2[2][NBUCKET][256];   // per-bucket col {sum, sumsq}
__device__ float g_bnS[H];
__device__ float g_bnH[H];

// ---------------------------------------------------------------------------
// dtype probe: int64 edge_index has zero high-words at odd int32 positions.
__global__ void probe_kernel(const int* __restrict__ ei32, int e) {
    __shared__ int nz;
    if (threadIdx.x == 0) nz = 0;
    __syncthreads();
    int pos = 2 * threadIdx.x + 1;
    if (pos < 2 * e && ei32[pos] != 0) atomicAdd(&nz, 1);
    __syncthreads();
    if (threadIdx.x == 0) g_is64 = (nz == 0) ? 1 : 0;
}

__device__ __forceinline__ int load_idx(const void* eiv, size_t pos, int n) {
    int v;
    if (g_is64) v = (int)((const long long*)eiv)[pos];
    else        v = ((const int*)eiv)[pos];
    return min(max(v, 0), n - 1);
}

// ---------------------------------------------------------------------------
__global__ void zero_kernel(int n) {
    int i = blockIdx.x * blockDim.x + threadIdx.x;
    if (i < n) g_deg[i] = 0;
    if (i < 2 * NBUCKET * 256) ((float*)g_stats2)[i] = 0.0f;
}

__global__ void count_kernel(const void* __restrict__ eiv, int e, int n) {
    int i = blockIdx.x * blockDim.x + threadIdx.x;
    if (i < e) {
        int d = load_idx(eiv, (size_t)e + i, n);
        atomicAdd(&g_deg[d], 1);
    }
}

// phase 1: per-block sums of g_deg
__global__ void scan1_kernel(int n) {
    __shared__ int ws[8];
    int i = blockIdx.x * SB + threadIdx.x;
    int v = (i < n) ? g_deg[i] : 0;
    #pragma unroll
    for (int o = 16; o > 0; o >>= 1) v += __shfl_down_sync(0xffffffffu, v, o);
    if ((threadIdx.x & 31) == 0) ws[threadIdx.x >> 5] = v;
    __syncthreads();
    if (threadIdx.x < 8) {
        int s = ws[threadIdx.x];
        #pragma unroll
        for (int o = 4; o > 0; o >>= 1) s += __shfl_down_sync(0xffu, s, o);
        if (threadIdx.x == 0) g_bsum[blockIdx.x] = s;
    }
}

// phase 2: exclusive scan of block sums
__global__ void scan2_kernel(int nb) {
    __shared__ int sh[NBMAX];
    int t = threadIdx.x;
    if (t < nb) sh[t] = g_bsum[t];
    __syncthreads();
    for (int o = 1; o < nb; o <<= 1) {
        int v = (t >= o && t < nb) ? sh[t - o] : 0;
        __syncthreads();
        if (t < nb) sh[t] += v;
        __syncthreads();
    }
    if (t < nb) g_bbase[t] = (t > 0) ? sh[t - 1] : 0;
}

// phase 3: per-block local exclusive scan + base -> offs/cur; also dinv
__global__ void scan3_kernel(int n) {
    __shared__ int sh[SB];
    int t = threadIdx.x;
    int i = blockIdx.x * SB + t;
    int d = (i < n) ? g_deg[i] : 0;
    sh[t] = d;
    __syncthreads();
    #pragma unroll
    for (int o = 1; o < SB; o <<= 1) {
        int v = (t >= o) ? sh[t - o] : 0;
        __syncthreads();
        sh[t] += v;
        __syncthreads();
    }
    int incl = sh[t];
    int base = g_bbase[blockIdx.x];
    if (i < n) {
        int off = base + incl - d;
        g_offs[i] = off;
        g_cur[i] = off;
        g_dinv[i] = rsqrtf((float)d + 1.0f);
        if (i == n - 1) g_offs[n] = base + incl;
    }
}

__global__ void fill_kernel(const void* __restrict__ eiv, int e, int n) {
    int i = blockIdx.x * blockDim.x + threadIdx.x;
    if (i < e) {
        int s = load_idx(eiv, (size_t)i, n);
        int d = load_idx(eiv, (size_t)e + i, n);
        int p = atomicAdd(&g_cur[d], 1);
        if (p >= 0 && p < EMAX) g_adj[p] = s;
    }
}

// ---------------------------------------------------------------------------
// GEMM: g_hh[row] = dinv[row] * ( f(X[row]) @ W )
// 128x128 tile, 256 threads, 4 rows x 16 cols/thread, fma.rn.f32x2,
// register-prefetch double buffering across the 4 K-chunks.
#define KC 32
__global__ void __launch_bounds__(256)
gemm_kernel(const float* __restrict__ Xext, const float* __restrict__ W,
            int n, int mode) {
    __shared__ float Xs[128][KC + 1];
    __shared__ float Ws[KC][128];
    __shared__ float bnS[H], bnH[H];

    const float* X = (mode == 1) ? (const float*)g_y : Xext;

    int tid = threadIdx.x;
    int row0 = blockIdx.x * 128;
    int tx = tid & 7;
    int ty = tid >> 3;

    if (tid < 128) { bnS[tid] = g_bnS[tid]; bnH[tid] = g_bnH[tid]; }

    // per-chunk staging indices (4 float4 each for X and W)
    int xr[4], xc[4], wr[4], wc[4];
    #pragma unroll
    for (int u = 0; u < 4; u++) {
        int i = tid + u * 256;
        xr[u] = i >> 3;  xc[u] = i & 7;    // X: 128 rows x 8 float4
        wr[u] = i >> 5;  wc[u] = i & 31;   // W: 32 rows x 32 float4
    }

    float4 xv[4], wv[4];
    // prologue: load chunk 0
    #pragma unroll
    for (int u = 0; u < 4; u++) {
        int grow = row0 + xr[u];
        xv[u] = (grow < n) ? *(const float4*)(X + (size_t)grow * H + xc[u] * 4)
                           : make_float4(0.f, 0.f, 0.f, 0.f);
        wv[u] = *(const float4*)(W + (size_t)wr[u] * H + wc[u] * 4);
    }

    unsigned long long acc[4][8];
    #pragma unroll
    for (int r = 0; r < 4; r++)
        #pragma unroll
        for (int j = 0; j < 8; j++) acc[r][j] = 0ull;

    #pragma unroll
    for (int cch = 0; cch < 4; cch++) {
        int kc = cch * KC;
        __syncthreads();   // prev compute done; safe to overwrite smem
        #pragma unroll
        for (int u = 0; u < 4; u++) {
            float4 v = xv[u];
            if (mode == 1) {
                int c = kc + xc[u] * 4;
                v.x = fmaxf(fmaf(v.x, bnS[c + 0], bnH[c + 0]), 0.f);
                v.y = fmaxf(fmaf(v.y, bnS[c + 1], bnH[c + 1]), 0.f);
                v.z = fmaxf(fmaf(v.z, bnS[c + 2], bnH[c + 2]), 0.f);
                v.w = fmaxf(fmaf(v.w, bnS[c + 3], bnH[c + 3]), 0.f);
            }
            Xs[xr[u]][xc[u] * 4 + 0] = v.x;
            Xs[xr[u]][xc[u] * 4 + 1] = v.y;
            Xs[xr[u]][xc[u] * 4 + 2] = v.z;
            Xs[xr[u]][xc[u] * 4 + 3] = v.w;
            *(float4*)&Ws[wr[u]][wc[u] * 4] = wv[u];
        }
        __syncthreads();

        if (cch < 3) {   // prefetch next chunk while computing this one
            int kn = kc + KC;
            #pragma unroll
            for (int u = 0; u < 4; u++) {
                int grow = row0 + xr[u];
                xv[u] = (grow < n)
                    ? *(const float4*)(X + (size_t)grow * H + kn + xc[u] * 4)
                    : make_float4(0.f, 0.f, 0.f, 0.f);
                wv[u] = *(const float4*)(W + (size_t)(kn + wr[u]) * H + wc[u] * 4);
            }
        }

        #pragma unroll
        for (int k = 0; k < KC; k++) {
            unsigned long long a[4];
            #pragma unroll
            for (int r = 0; r < 4; r++) {
                unsigned int ai = __float_as_uint(Xs[ty * 4 + r][k]);
                asm("mov.b64 %0, {%1, %1};" : "=l"(a[r]) : "r"(ai));
            }
            const unsigned long long* bp = (const unsigned long long*)&Ws[k][0];
            unsigned long long b[8];
            #pragma unroll
            for (int j = 0; j < 8; j++) b[j] = bp[j * 8 + tx];
            #pragma unroll
            for (int r = 0; r < 4; r++)
                #pragma unroll
                for (int j = 0; j < 8; j++)
                    asm("fma.rn.f32x2 %0, %1, %2, %0;"
                        : "+l"(acc[r][j]) : "l"(a[r]), "l"(b[j]));
        }
    }

    #pragma unroll
    for (int r = 0; r < 4; r++) {
        int row = row0 + ty * 4 + r;
        if (row < n) {
            float dv = g_dinv[row];
            float* o = g_hh + (size_t)row * H + tx * 2;
            #pragma unroll
            for (int j = 0; j < 8; j++) {
                unsigned int lo, hi;
                asm("mov.b64 {%0, %1}, %2;" : "=r"(lo), "=r"(hi) : "l"(acc[r][j]));
                float2 v;
                v.x = __uint_as_float(lo) * dv;
                v.y = __uint_as_float(hi) * dv;
                *(float2*)(o + j * 16) = v;
            }
        }
    }
}

// ---------------------------------------------------------------------------
// aggregation + fused BN stats: one warp per node (8 nodes/block).
// y[d] = dinv[d]*(hh[d] + sum_{s in N(d)} hh[s]) + bias; block reduces its
// 8 rows and atomically adds into stats bucket [blockIdx % NBUCKET].
__global__ void __launch_bounds__(256)
agg_kernel(const float* __restrict__ bias, int n, int slot) {
    __shared__ float red[8][128];
    __shared__ float redq[8][128];

    int w = threadIdx.x >> 5;
    int lane = threadIdx.x & 31;
    int d = blockIdx.x * 8 + w;
    bool active = d < n;

    float4 out = make_float4(0.f, 0.f, 0.f, 0.f);
    if (active) {
        const float4* hh4 = (const float4*)g_hh;
        float4 acc = hh4[(size_t)d * 32 + lane];   // self-loop term
        int beg = g_offs[d];
        int end = g_offs[d + 1];

        for (int j0 = beg; j0 < end; j0 += 32) {
            int idx = (j0 + lane < end) ? g_adj[j0 + lane] : 0;
            int cnt = min(32, end - j0);
            int t = 0;
            for (; t + 3 < cnt; t += 4) {
                int s0 = __shfl_sync(0xffffffffu, idx, t + 0);
                int s1 = __shfl_sync(0xffffffffu, idx, t + 1);
                int s2 = __shfl_sync(0xffffffffu, idx, t + 2);
                int s3 = __shfl_sync(0xffffffffu, idx, t + 3);
                float4 v0 = hh4[(size_t)s0 * 32 + lane];
                float4 v1 = hh4[(size_t)s1 * 32 + lane];
                float4 v2 = hh4[(size_t)s2 * 32 + lane];
                float4 v3 = hh4[(size_t)s3 * 32 + lane];
                acc.x += v0.x + v1.x + v2.x + v3.x;
                acc.y += v0.y + v1.y + v2.y + v3.y;
                acc.z += v0.z + v1.z + v2.z + v3.z;
                acc.w += v0.w + v1.w + v2.w + v3.w;
            }
            for (; t < cnt; t++) {
                int s = __shfl_sync(0xffffffffu, idx, t);
                float4 v = hh4[(size_t)s * 32 + lane];
                acc.x += v.x; acc.y += v.y; acc.z += v.z; acc.w += v.w;
            }
        }

        float dv = g_dinv[d];
        float4 bb = *(const float4*)(bias + lane * 4);
        out.x = fmaf(acc.x, dv, bb.x);
        out.y = fmaf(acc.y, dv, bb.y);
        out.z = fmaf(acc.z, dv, bb.z);
        out.w = fmaf(acc.w, dv, bb.w);
        ((float4*)g_y)[(size_t)d * 32 + lane] = out;
    }

    red[w][lane * 4 + 0] = out.x;  redq[w][lane * 4 + 0] = out.x * out.x;
    red[w][lane * 4 + 1] = out.y;  redq[w][lane * 4 + 1] = out.y * out.y;
    red[w][lane * 4 + 2] = out.z;  redq[w][lane * 4 + 2] = out.z * out.z;
    red[w][lane * 4 + 3] = out.w;  redq[w][lane * 4 + 3] = out.w * out.w;
    __syncthreads();

    int tid = threadIdx.x;
    if (tid < 128) {
        float s = 0.f, q = 0.f;
        #pragma unroll
        for (int i = 0; i < 8; i++) { s += red[i][tid]; q += redq[i][tid]; }
        float* bucket = &g_stats2[slot][blockIdx.x & (NBUCKET - 1)][0];
        atomicAdd(&bucket[tid], s);
        atomicAdd(&bucket[128 + tid], q);
    }
}

// ---------------------------------------------------------------------------
// reduce buckets -> BN affine params
__global__ void bnreduce_kernel(const float* __restrict__ g,
                                const float* __restrict__ beta,
                                int n, int slot) {
    int c = threadIdx.x;  // 128
    float s = 0.f, q = 0.f;
    for (int b = 0; b < NBUCKET; b++) {
        s += g_stats2[slot][b][c];
        q += g_stats2[slot][b][128 + c];
    }
    float inv_n = 1.0f / (float)n;
    float mu = s * inv_n;
    float var = q * inv_n - mu * mu;
    float istd = rsqrtf(var + 1e-5f);
    float sc = g[c] * istd;
    g_bnS[c] = sc;
    g_bnH[c] = beta[c] - mu * sc;
}

__global__ void out_kernel(float* __restrict__ out, int n) {
    int i = blockIdx.x * blockDim.x + threadIdx.x;
    if (i >= n * 32) return;
    int c = (i & 31) * 4;
    float4 v = ((const float4*)g_y)[i];
    v.x = fmaxf(fmaf(v.x, g_bnS[c + 0], g_bnH[c + 0]), 0.f);
    v.y = fmaxf(fmaf(v.y, g_bnS[c + 1], g_bnH[c + 1]), 0.f);
    v.z = fmaxf(fmaf(v.z, g_bnS[c + 2], g_bnH[c + 2]), 0.f);
    v.w = fmaxf(fmaf(v.w, g_bnS[c + 3], g_bnH[c + 3]), 0.f);
    ((float4*)out)[i] = v;
}

// ---------------------------------------------------------------------------
extern "C" void kernel_launch(void* const* d_in, const int* in_sizes, int n_in,
                              void* d_out, int out_size) {
    const float* node_feat = (const float*)d_in[0];
    const void*  ei        = d_in[1];
    const float* W1   = (const float*)d_in[2];
    const float* b1   = (const float*)d_in[3];
    const float* W2   = (const float*)d_in[4];
    const float* b2   = (const float*)d_in[5];
    const float* g1   = (const float*)d_in[6];
    const float* beta1= (const float*)d_in[7];
    const float* g2   = (const float*)d_in[8];
    const float* beta2= (const float*)d_in[9];

    int n = in_sizes[0] / H;
    int e = in_sizes[1] / 2;

    int nb256 = (n + 255) / 256;
    int eb256 = (e + 255) / 256;
    int gemm_blocks = (n + 127) / 128;
    int agg_blocks = (n + 7) / 8;
    int scan_blocks = (n + SB - 1) / SB;

    // graph prep
    probe_kernel<<<1, 1024>>>((const int*)ei, e);
    zero_kernel<<<nb256, 256>>>(n);
    count_kernel<<<eb256, 256>>>(ei, e, n);
    scan1_kernel<<<scan_blocks, SB>>>(n);
    scan2_kernel<<<1, NBMAX>>>(scan_blocks);
    scan3_kernel<<<scan_blocks, SB>>>(n);
    fill_kernel<<<eb256, 256>>>(ei, e, n);

    // layer 1
    gemm_kernel<<<gemm_blocks, 256>>>(node_feat, W1, n, 0);
    agg_kernel<<<agg_blocks, 256>>>(b1, n, 0);
    bnreduce_kernel<<<1, 128>>>(g1, beta1, n, 0);

    // layer 2 (BN+relu fused into GEMM X-tile load)
    gemm_kernel<<<gemm_blocks, 256>>>(nullptr, W2, n, 1);
    agg_kernel<<<agg_blocks, 256>>>(b2, n, 1);
    bnreduce_kernel<<<1, 128>>>(g2, beta2, n, 1);

    out_kernel<<<(n * 32 + 255) / 256, 256>>>((float*)d_out, n);
}

// round 6
// speedup vs baseline: 2.1362x; 1.0871x over previous
#include <cuda_runtime.h>
#include <cuda_fp16.h>
#include <cstdint>

#define NMAX 50048
#define EMAX 800256
#define H 128
#define SB 256
#define NBMAX ((NMAX + SB - 1) / SB)
#define NBUCKET 64

__device__ int   g_is64;
__device__ int   g_deg[NMAX];
__device__ int   g_offs[NMAX + 1];
__device__ int   g_cur[NMAX];
__device__ int   g_adj[EMAX];
__device__ int   g_bsum[NBMAX];
__device__ int   g_bbase[NBMAX];
__device__ float g_dinv[NMAX];
__device__ __align__(16) __half g_hhh[(size_t)NMAX * H];   // fp16 staged xW*dinv
__device__ __align__(16) float  g_y[(size_t)NMAX * H];
__device__ float g_stats2[2][NBUCKET][256];
__device__ float g_bnS[H];
__device__ float g_bnH[H];

// ---------------------------------------------------------------------------
// dtype probe: int64 edge_index has zero high-words at odd int32 positions.
__global__ void probe_kernel(const int* __restrict__ ei32, int e) {
    __shared__ int nz;
    if (threadIdx.x == 0) nz = 0;
    __syncthreads();
    int pos = 2 * threadIdx.x + 1;
    if (pos < 2 * e && ei32[pos] != 0) atomicAdd(&nz, 1);
    __syncthreads();
    if (threadIdx.x == 0) g_is64 = (nz == 0) ? 1 : 0;
}

__device__ __forceinline__ int load_idx(const void* eiv, size_t pos, int n) {
    int v;
    if (g_is64) v = (int)((const long long*)eiv)[pos];
    else        v = ((const int*)eiv)[pos];
    return min(max(v, 0), n - 1);
}

// ---------------------------------------------------------------------------
__global__ void zero_kernel(int n) {
    int i = blockIdx.x * blockDim.x + threadIdx.x;
    if (i < n) g_deg[i] = 0;
    if (i < 2 * NBUCKET * 256) ((float*)g_stats2)[i] = 0.0f;
}

__global__ void count_kernel(const void* __restrict__ eiv, int e, int n) {
    int i = blockIdx.x * blockDim.x + threadIdx.x;
    if (i < e) {
        int d = load_idx(eiv, (size_t)e + i, n);
        atomicAdd(&g_deg[d], 1);
    }
}

__global__ void scan1_kernel(int n) {
    __shared__ int ws[8];
    int i = blockIdx.x * SB + threadIdx.x;
    int v = (i < n) ? g_deg[i] : 0;
    #pragma unroll
    for (int o = 16; o > 0; o >>= 1) v += __shfl_down_sync(0xffffffffu, v, o);
    if ((threadIdx.x & 31) == 0) ws[threadIdx.x >> 5] = v;
    __syncthreads();
    if (threadIdx.x < 8) {
        int s = ws[threadIdx.x];
        #pragma unroll
        for (int o = 4; o > 0; o >>= 1) s += __shfl_down_sync(0xffu, s, o);
        if (threadIdx.x == 0) g_bsum[blockIdx.x] = s;
    }
}

__global__ void scan2_kernel(int nb) {
    __shared__ int sh[NBMAX];
    int t = threadIdx.x;
    if (t < nb) sh[t] = g_bsum[t];
    __syncthreads();
    for (int o = 1; o < nb; o <<= 1) {
        int v = (t >= o && t < nb) ? sh[t - o] : 0;
        __syncthreads();
        if (t < nb) sh[t] += v;
        __syncthreads();
    }
    if (t < nb) g_bbase[t] = (t > 0) ? sh[t - 1] : 0;
}

__global__ void scan3_kernel(int n) {
    __shared__ int sh[SB];
    int t = threadIdx.x;
    int i = blockIdx.x * SB + t;
    int d = (i < n) ? g_deg[i] : 0;
    sh[t] = d;
    __syncthreads();
    #pragma unroll
    for (int o = 1; o < SB; o <<= 1) {
        int v = (t >= o) ? sh[t - o] : 0;
        __syncthreads();
        sh[t] += v;
        __syncthreads();
    }
    int incl = sh[t];
    int base = g_bbase[blockIdx.x];
    if (i < n) {
        int off = base + incl - d;
        g_offs[i] = off;
        g_cur[i] = off;
        g_dinv[i] = rsqrtf((float)d + 1.0f);
        if (i == n - 1) g_offs[n] = base + incl;
    }
}

__global__ void fill_kernel(const void* __restrict__ eiv, int e, int n) {
    int i = blockIdx.x * blockDim.x + threadIdx.x;
    if (i < e) {
        int s = load_idx(eiv, (size_t)i, n);
        int d = load_idx(eiv, (size_t)e + i, n);
        int p = atomicAdd(&g_cur[d], 1);
        if (p >= 0 && p < EMAX) g_adj[p] = s;
    }
}

// ---------------------------------------------------------------------------
// GEMM: g_hhh[row] = fp16( dinv[row] * ( f(X[row]) @ W ) )
// 128x128 tile, 256 threads, 4 rows x 16 cols/thread, fma.rn.f32x2,
// register-prefetch double buffering across the 4 K-chunks.
#define KC 32
__global__ void __launch_bounds__(256)
gemm_kernel(const float* __restrict__ Xext, const float* __restrict__ W,
            int n, int mode) {
    __shared__ float Xs[128][KC + 1];
    __shared__ float Ws[KC][128];
    __shared__ float bnS[H], bnH[H];

    const float* X = (mode == 1) ? (const float*)g_y : Xext;

    int tid = threadIdx.x;
    int row0 = blockIdx.x * 128;
    int tx = tid & 7;
    int ty = tid >> 3;

    if (tid < 128) { bnS[tid] = g_bnS[tid]; bnH[tid] = g_bnH[tid]; }

    int xr[4], xc[4], wr[4], wc[4];
    #pragma unroll
    for (int u = 0; u < 4; u++) {
        int i = tid + u * 256;
        xr[u] = i >> 3;  xc[u] = i & 7;
        wr[u] = i >> 5;  wc[u] = i & 31;
    }

    float4 xv[4], wv[4];
    #pragma unroll
    for (int u = 0; u < 4; u++) {
        int grow = row0 + xr[u];
        xv[u] = (grow < n) ? *(const float4*)(X + (size_t)grow * H + xc[u] * 4)
                           : make_float4(0.f, 0.f, 0.f, 0.f);
        wv[u] = *(const float4*)(W + (size_t)wr[u] * H + wc[u] * 4);
    }

    unsigned long long acc[4][8];
    #pragma unroll
    for (int r = 0; r < 4; r++)
        #pragma unroll
        for (int j = 0; j < 8; j++) acc[r][j] = 0ull;

    #pragma unroll
    for (int cch = 0; cch < 4; cch++) {
        int kc = cch * KC;
        __syncthreads();
        #pragma unroll
        for (int u = 0; u < 4; u++) {
            float4 v = xv[u];
            if (mode == 1) {
                int c = kc + xc[u] * 4;
                v.x = fmaxf(fmaf(v.x, bnS[c + 0], bnH[c + 0]), 0.f);
                v.y = fmaxf(fmaf(v.y, bnS[c + 1], bnH[c + 1]), 0.f);
                v.z = fmaxf(fmaf(v.z, bnS[c + 2], bnH[c + 2]), 0.f);
                v.w = fmaxf(fmaf(v.w, bnS[c + 3], bnH[c + 3]), 0.f);
            }
            Xs[xr[u]][xc[u] * 4 + 0] = v.x;
            Xs[xr[u]][xc[u] * 4 + 1] = v.y;
            Xs[xr[u]][xc[u] * 4 + 2] = v.z;
            Xs[xr[u]][xc[u] * 4 + 3] = v.w;
            *(float4*)&Ws[wr[u]][wc[u] * 4] = wv[u];
        }
        __syncthreads();

        if (cch < 3) {
            int kn = kc + KC;
            #pragma unroll
            for (int u = 0; u < 4; u++) {
                int grow = row0 + xr[u];
                xv[u] = (grow < n)
                    ? *(const float4*)(X + (size_t)grow * H + kn + xc[u] * 4)
                    : make_float4(0.f, 0.f, 0.f, 0.f);
                wv[u] = *(const float4*)(W + (size_t)(kn + wr[u]) * H + wc[u] * 4);
            }
        }

        #pragma unroll
        for (int k = 0; k < KC; k++) {
            unsigned long long a[4];
            #pragma unroll
            for (int r = 0; r < 4; r++) {
                unsigned int ai = __float_as_uint(Xs[ty * 4 + r][k]);
                asm("mov.b64 %0, {%1, %1};" : "=l"(a[r]) : "r"(ai));
            }
            const unsigned long long* bp = (const unsigned long long*)&Ws[k][0];
            unsigned long long b[8];
            #pragma unroll
            for (int j = 0; j < 8; j++) b[j] = bp[j * 8 + tx];
            #pragma unroll
            for (int r = 0; r < 4; r++)
                #pragma unroll
                for (int j = 0; j < 8; j++)
                    asm("fma.rn.f32x2 %0, %1, %2, %0;"
                        : "+l"(acc[r][j]) : "l"(a[r]), "l"(b[j]));
        }
    }

    #pragma unroll
    for (int r = 0; r < 4; r++) {
        int row = row0 + ty * 4 + r;
        if (row < n) {
            float dv = g_dinv[row];
            __half* o = g_hhh + (size_t)row * H + tx * 2;
            #pragma unroll
            for (int j = 0; j < 8; j++) {
                unsigned int lo, hi;
                asm("mov.b64 {%0, %1}, %2;" : "=r"(lo), "=r"(hi) : "l"(acc[r][j]));
                __half2 h = __floats2half2_rn(__uint_as_float(lo) * dv,
                                              __uint_as_float(hi) * dv);
                *(__half2*)(o + j * 16) = h;
            }
        }
    }
}

// ---------------------------------------------------------------------------
// aggregation + fused BN stats: one warp per node, fp16 gather (uint2/lane =
// 4 halves, warp covers 128 cols), fp32 accumulate.
__global__ void __launch_bounds__(256)
agg_kernel(const float* __restrict__ bias, int n, int slot) {
    __shared__ float red[8][128];
    __shared__ float redq[8][128];

    int w = threadIdx.x >> 5;
    int lane = threadIdx.x & 31;
    int d = blockIdx.x * 8 + w;
    bool active = d < n;

    float4 out = make_float4(0.f, 0.f, 0.f, 0.f);
    if (active) {
        const uint2* hh2 = (const uint2*)g_hhh;   // 32 uint2 per row
        float4 acc;
        {
            uint2 v = hh2[(size_t)d * 32 + lane];  // self-loop term
            float2 p0 = __half22float2(*(const __half2*)&v.x);
            float2 p1 = __half22float2(*(const __half2*)&v.y);
            acc = make_float4(p0.x, p0.y, p1.x, p1.y);
        }
        int beg = g_offs[d];
        int end = g_offs[d + 1];

        for (int j0 = beg; j0 < end; j0 += 32) {
            int idx = (j0 + lane < end) ? g_adj[j0 + lane] : 0;
            int cnt = min(32, end - j0);
            int t = 0;
            for (; t + 3 < cnt; t += 4) {
                int s0 = __shfl_sync(0xffffffffu, idx, t + 0);
                int s1 = __shfl_sync(0xffffffffu, idx, t + 1);
                int s2 = __shfl_sync(0xffffffffu, idx, t + 2);
                int s3 = __shfl_sync(0xffffffffu, idx, t + 3);
                uint2 v0 = hh2[(size_t)s0 * 32 + lane];
                uint2 v1 = hh2[(size_t)s1 * 32 + lane];
                uint2 v2 = hh2[(size_t)s2 * 32 + lane];
                uint2 v3 = hh2[(size_t)s3 * 32 + lane];
                float2 a0 = __half22float2(*(const __half2*)&v0.x);
                float2 b0 = __half22float2(*(const __half2*)&v0.y);
                float2 a1 = __half22float2(*(const __half2*)&v1.x);
                float2 b1 = __half22float2(*(const __half2*)&v1.y);
                float2 a2 = __half22float2(*(const __half2*)&v2.x);
                float2 b2 = __half22float2(*(const __half2*)&v2.y);
                float2 a3 = __half22float2(*(const __half2*)&v3.x);
                float2 b3 = __half22float2(*(const __half2*)&v3.y);
                acc.x += (a0.x + a1.x) + (a2.x + a3.x);
                acc.y += (a0.y + a1.y) + (a2.y + a3.y);
                acc.z += (b0.x + b1.x) + (b2.x + b3.x);
                acc.w += (b0.y + b1.y) + (b2.y + b3.y);
            }
            for (; t < cnt; t++) {
                int s = __shfl_sync(0xffffffffu, idx, t);
                uint2 v = hh2[(size_t)s * 32 + lane];
                float2 a = __half22float2(*(const __half2*)&v.x);
                float2 b = __half22float2(*(const __half2*)&v.y);
                acc.x += a.x; acc.y += a.y; acc.z += b.x; acc.w += b.y;
            }
        }

        float dv = g_dinv[d];
        float4 bb = *(const float4*)(bias + lane * 4);
        out.x = fmaf(acc.x, dv, bb.x);
        out.y = fmaf(acc.y, dv, bb.y);
        out.z = fmaf(acc.z, dv, bb.z);
        out.w = fmaf(acc.w, dv, bb.w);
        ((float4*)g_y)[(size_t)d * 32 + lane] = out;
    }

    red[w][lane * 4 + 0] = out.x;  redq[w][lane * 4 + 0] = out.x * out.x;
    red[w][lane * 4 + 1] = out.y;  redq[w][lane * 4 + 1] = out.y * out.y;
    red[w][lane * 4 + 2] = out.z;  redq[w][lane * 4 + 2] = out.z * out.z;
    red[w][lane * 4 + 3] = out.w;  redq[w][lane * 4 + 3] = out.w * out.w;
    __syncthreads();

    int tid = threadIdx.x;
    if (tid < 128) {
        float s = 0.f, q = 0.f;
        #pragma unroll
        for (int i = 0; i < 8; i++) { s += red[i][tid]; q += redq[i][tid]; }
        float* bucket = &g_stats2[slot][blockIdx.x & (NBUCKET - 1)][0];
        atomicAdd(&bucket[tid], s);
        atomicAdd(&bucket[128 + tid], q);
    }
}

// ---------------------------------------------------------------------------
__global__ void bnreduce_kernel(const float* __restrict__ g,
                                const float* __restrict__ beta,
                                int n, int slot) {
    int c = threadIdx.x;
    float s = 0.f, q = 0.f;
    for (int b = 0; b < NBUCKET; b++) {
        s += g_stats2[slot][b][c];
        q += g_stats2[slot][b][128 + c];
    }
    float inv_n = 1.0f / (float)n;
    float mu = s * inv_n;
    float var = q * inv_n - mu * mu;
    float istd = rsqrtf(var + 1e-5f);
    float sc = g[c] * istd;
    g_bnS[c] = sc;
    g_bnH[c] = beta[c] - mu * sc;
}

__global__ void out_kernel(float* __restrict__ out, int n) {
    int i = blockIdx.x * blockDim.x + threadIdx.x;
    if (i >= n * 32) return;
    int c = (i & 31) * 4;
    float4 v = ((const float4*)g_y)[i];
    v.x = fmaxf(fmaf(v.x, g_bnS[c + 0], g_bnH[c + 0]), 0.f);
    v.y = fmaxf(fmaf(v.y, g_bnS[c + 1], g_bnH[c + 1]), 0.f);
    v.z = fmaxf(fmaf(v.z, g_bnS[c + 2], g_bnH[c + 2]), 0.f);
    v.w = fmaxf(fmaf(v.w, g_bnS[c + 3], g_bnH[c + 3]), 0.f);
    ((float4*)out)[i] = v;
}

// ---------------------------------------------------------------------------
extern "C" void kernel_launch(void* const* d_in, const int* in_sizes, int n_in,
                              void* d_out, int out_size) {
    const float* node_feat = (const float*)d_in[0];
    const void*  ei        = d_in[1];
    const float* W1   = (const float*)d_in[2];
    const float* b1   = (const float*)d_in[3];
    const float* W2   = (const float*)d_in[4];
    const float* b2   = (const float*)d_in[5];
    const float* g1   = (const float*)d_in[6];
    const float* beta1= (const float*)d_in[7];
    const float* g2   = (const float*)d_in[8];
    const float* beta2= (const float*)d_in[9];

    int n = in_sizes[0] / H;
    int e = in_sizes[1] / 2;

    int nb256 = (n + 255) / 256;
    int eb256 = (e + 255) / 256;
    int gemm_blocks = (n + 127) / 128;
    int agg_blocks = (n + 7) / 8;
    int scan_blocks = (n + SB - 1) / SB;

    probe_kernel<<<1, 1024>>>((const int*)ei, e);
    zero_kernel<<<nb256, 256>>>(n);
    count_kernel<<<eb256, 256>>>(ei, e, n);
    scan1_kernel<<<scan_blocks, SB>>>(n);
    scan2_kernel<<<1, NBMAX>>>(scan_blocks);
    scan3_kernel<<<scan_blocks, SB>>>(n);
    fill_kernel<<<eb256, 256>>>(ei, e, n);

    gemm_kernel<<<gemm_blocks, 256>>>(node_feat, W1, n, 0);
    agg_kernel<<<agg_blocks, 256>>>(b1, n, 0);
    bnreduce_kernel<<<1, 128>>>(g1, beta1, n, 0);

    gemm_kernel<<<gemm_blocks, 256>>>(nullptr, W2, n, 1);
    agg_kernel<<<agg_blocks, 256>>>(b2, n, 1);
    bnreduce_kernel<<<1, 128>>>(g2, beta2, n, 1);

    out_kernel<<<(n * 32 + 255) / 256, 256>>>((float*)d_out, n);
}